// round 16
// baseline (speedup 1.0000x reference)
#include <cuda_runtime.h>
#include <cuda_bf16.h>
#include <math.h>

// OmegaRule: B=8, L=8192, D=256, W=64 -> NW=128 windows, T=B*W=512 rows/window.
#define BB 8
#define LL 8192
#define DD 256
#define WW 64
#define NW 128
#define TT 512
#define CH 16    // chunks
#define CS 8     // windows per chunk (CH*CS == NW)
#define MATSZ (DD * DD)
#define MATW (MATSZ / 2)   // matrix size in bf16-pair words
#define K1_SMEM (6 * 64 * 36 * 4)

// Scratch (device globals; no allocation allowed).
__device__ float g_Skk[NW * MATSZ];
__device__ float g_Svk[NW * MATSZ];
__device__ float g_Ms [NW * MATSZ];
__device__ float g_P  [NW * MATSZ];
__device__ float g_TP0[CH * MATSZ];
__device__ float g_TP1[CH * MATSZ];
__device__ float g_TS0[CH * MATSZ];
__device__ float g_TS1[CH * MATSZ];
// bf16 hi/lo word-packed buffers (low half = even index)
__device__ __align__(16) unsigned g_Qh [BB * LL * DD / 2];
__device__ __align__(16) unsigned g_Ql [BB * LL * DD / 2];
__device__ __align__(16) unsigned g_Msh[NW * MATW];
__device__ __align__(16) unsigned g_Msl[NW * MATW];
__device__ __align__(16) unsigned g_PTh[NW * MATW];   // transposed P: PT[y][d]
__device__ __align__(16) unsigned g_PTl[NW * MATW];
__device__ __align__(16) unsigned g_Eh [CH * MATW];
__device__ __align__(16) unsigned g_El [CH * MATW];

typedef unsigned long long u64;
__device__ __forceinline__ void ffma2(u64& acc, u64 a, u64 b) {
    asm("fma.rn.f32x2 %0, %1, %2, %0;" : "+l"(acc) : "l"(a), "l"(b));
}
__device__ __forceinline__ u64 pack2f(float x, float y) {
    u64 r; asm("mov.b64 %0, {%1, %2};" : "=l"(r) : "f"(x), "f"(y)); return r;
}
__device__ __forceinline__ void unpack2f(u64 v, float& x, float& y) {
    asm("mov.b64 {%0, %1}, %2;" : "=f"(x), "=f"(y) : "l"(v));
}
__device__ __forceinline__ float hsum2(u64 v) {
    float x, y; unpack2f(v, x, y); return x + y;
}

// bf16 pair pack: low half = x (even index), high half = y (odd index).
__device__ __forceinline__ unsigned pack_bf16(float x, float y) {
    __nv_bfloat162 h = __floats2bfloat162_rn(x, y);
    return *(unsigned*)&h;
}
__device__ __forceinline__ float bf_hi_f(float x) {
    return __bfloat162float(__float2bfloat16(x));
}

// m16n8k16 bf16 MMA, fp32 accumulate (row.col).
__device__ __forceinline__ void mma_bf16(float* c, const unsigned* a, const unsigned* b) {
    asm volatile(
        "mma.sync.aligned.m16n8k16.row.col.f32.bf16.bf16.f32 "
        "{%0,%1,%2,%3}, {%4,%5,%6,%7}, {%8,%9}, {%0,%1,%2,%3};"
        : "+f"(c[0]), "+f"(c[1]), "+f"(c[2]), "+f"(c[3])
        : "r"(a[0]), "r"(a[1]), "r"(a[2]), "r"(a[3]), "r"(b[0]), "r"(b[1]));
}

// ---------------------------------------------------------------------------
// Conversion kernels (bandwidth-bound).
// ---------------------------------------------------------------------------
__global__ __launch_bounds__(256) void kConvQ(const float* __restrict__ q)
{
    const long i = ((long)blockIdx.x * 256 + threadIdx.x) * 4;
    float4 v = *(const float4*)(q + i);
    float h0 = bf_hi_f(v.x), h1 = bf_hi_f(v.y), h2 = bf_hi_f(v.z), h3 = bf_hi_f(v.w);
    g_Qh[i / 2 + 0] = pack_bf16(v.x, v.y);
    g_Qh[i / 2 + 1] = pack_bf16(v.z, v.w);
    g_Ql[i / 2 + 0] = pack_bf16(v.x - h0, v.y - h1);
    g_Ql[i / 2 + 1] = pack_bf16(v.z - h2, v.w - h3);
}

__global__ __launch_bounds__(256) void kConvM()
{
    const long i = ((long)blockIdx.x * 256 + threadIdx.x) * 4;
    float4 v = *(const float4*)(g_Ms + i);
    float h0 = bf_hi_f(v.x), h1 = bf_hi_f(v.y), h2 = bf_hi_f(v.z), h3 = bf_hi_f(v.w);
    g_Msh[i / 2 + 0] = pack_bf16(v.x, v.y);
    g_Msh[i / 2 + 1] = pack_bf16(v.z, v.w);
    g_Msl[i / 2 + 0] = pack_bf16(v.x - h0, v.y - h1);
    g_Msl[i / 2 + 1] = pack_bf16(v.z - h2, v.w - h3);
}

__global__ __launch_bounds__(256) void kTrE()
{
    const long i = ((long)blockIdx.x * 256 + threadIdx.x) * 4;
    float4 v = *(const float4*)(g_TS0 + i);
    float h0 = bf_hi_f(v.x), h1 = bf_hi_f(v.y), h2 = bf_hi_f(v.z), h3 = bf_hi_f(v.w);
    g_Eh[i / 2 + 0] = pack_bf16(v.x, v.y);
    g_Eh[i / 2 + 1] = pack_bf16(v.z, v.w);
    g_El[i / 2 + 0] = pack_bf16(v.x - h0, v.y - h1);
    g_El[i / 2 + 1] = pack_bf16(v.z - h2, v.w - h3);
}

// Transpose+convert P (windows CS..NW-1): PT[y][d] = P[d][y], bf16 hi/lo.
__global__ void kTrP()
{
    __shared__ float tile[32][33];
    const int n  = CS + blockIdx.y;
    const int dB = (blockIdx.x & 7) * 32;
    const int yB = (blockIdx.x >> 3) * 32;
    const int tx = threadIdx.x, ty = threadIdx.y;

    const float* P = g_P + (long)n * MATSZ;
    #pragma unroll
    for (int j = 0; j < 4; ++j)
        tile[ty + j * 8][tx] = P[(long)(dB + ty + j * 8) * DD + yB + tx];
    __syncthreads();

    if (tx < 16) {
        #pragma unroll
        for (int j = 0; j < 4; ++j) {
            const int yl = ty + j * 8;
            const float e0 = tile[2 * tx][yl];
            const float e1 = tile[2 * tx + 1][yl];
            const long w = (long)n * MATW + (long)(yB + yl) * (DD / 2) + dB / 2 + tx;
            g_PTh[w] = pack_bf16(e0, e1);
            g_PTl[w] = pack_bf16(e0 - bf_hi_f(e0), e1 - bf_hi_f(e1));
        }
    }
}

// ---------------------------------------------------------------------------
// K1 (NEW): per-window moment matrices via bf16x3 tensor-core MMA.
//   Svk[x][y] = sum_t (g v)[t][x] * k[t][y]   (all 16 tiles)
//   Skk[x][y] = sum_t (g k)[t][x] * k[t][y]   (ib<=jb, mirrored)
// Operands transposed+converted in smem to [feat][t] bf16 hi/lo.
// Each 64-t chunk == one batch b (rows contiguous). Dynamic smem 55 KB.
// ---------------------------------------------------------------------------
__global__ __launch_bounds__(256) void k1_moments(
    const float* __restrict__ keys,
    const float* __restrict__ values,
    const float* __restrict__ gammas)
{
    extern __shared__ unsigned sm1[];
    unsigned* sBh = sm1;               // k  (y-block rows)
    unsigned* sBl = sBh + 2304;
    unsigned* sVh = sBl + 2304;        // g*v (x-block rows)
    unsigned* sVl = sVh + 2304;
    unsigned* sKh = sVl + 2304;        // g*k (x-block rows)
    unsigned* sKl = sKh + 2304;
    __nv_bfloat16* hBh = (__nv_bfloat16*)sBh;
    __nv_bfloat16* hBl = (__nv_bfloat16*)sBl;
    __nv_bfloat16* hVh = (__nv_bfloat16*)sVh;
    __nv_bfloat16* hVl = (__nv_bfloat16*)sVl;
    __nv_bfloat16* hKh = (__nv_bfloat16*)sKh;
    __nv_bfloat16* hKl = (__nv_bfloat16*)sKl;

    const int n   = blockIdx.y;
    const int ib  = blockIdx.x >> 2;
    const int jb  = blockIdx.x & 3;
    const bool doSkk = (ib <= jb);
    const int tid = threadIdx.x;
    const int wid = tid >> 5;
    const int lane = tid & 31;
    const int gq  = lane >> 2;
    const int q4  = lane & 3;
    const int m0  = (wid >> 2) * 32;
    const int n0  = (wid & 3) * 16;
    const int w   = tid >> 2;     // t-in-chunk 0..63
    const int cseg = tid & 3;     // 16-col segment

    float Cv[2][2][4], Csm[2][2][4];
    #pragma unroll
    for (int mi = 0; mi < 2; ++mi)
        #pragma unroll
        for (int ni = 0; ni < 2; ++ni)
            #pragma unroll
            for (int e = 0; e < 4; ++e) { Cv[mi][ni][e] = 0.f; Csm[mi][ni][e] = 0.f; }

    for (int chu = 0; chu < 8; ++chu) {   // batch b == chu
        const long rbase = ((long)chu * LL + (long)n * WW + w) * DD;
        const float gm = __ldg(&gammas[(long)chu * LL + (long)n * WW + w]);

        #pragma unroll
        for (int f = 0; f < 4; ++f) {
            const int c0 = cseg * 16 + f * 4;
            float4 ky = *(const float4*)(keys   + rbase + jb * 64 + c0);
            float4 vv = *(const float4*)(values + rbase + ib * 64 + c0);
            float ke[4] = {ky.x, ky.y, ky.z, ky.w};
            float ve[4] = {gm * vv.x, gm * vv.y, gm * vv.z, gm * vv.w};
            #pragma unroll
            for (int e = 0; e < 4; ++e) {
                const int col = c0 + e;
                __nv_bfloat16 hk = __float2bfloat16(ke[e]);
                hBh[col * 72 + w] = hk;
                hBl[col * 72 + w] = __float2bfloat16(ke[e] - __bfloat162float(hk));
                __nv_bfloat16 hv = __float2bfloat16(ve[e]);
                hVh[col * 72 + w] = hv;
                hVl[col * 72 + w] = __float2bfloat16(ve[e] - __bfloat162float(hv));
            }
            if (doSkk) {
                float4 kx = *(const float4*)(keys + rbase + ib * 64 + c0);
                float ge[4] = {gm * kx.x, gm * kx.y, gm * kx.z, gm * kx.w};
                #pragma unroll
                for (int e = 0; e < 4; ++e) {
                    const int col = c0 + e;
                    __nv_bfloat16 hg = __float2bfloat16(ge[e]);
                    hKh[col * 72 + w] = hg;
                    hKl[col * 72 + w] = __float2bfloat16(ge[e] - __bfloat162float(hg));
                }
            }
        }
        __syncthreads();

        #pragma unroll
        for (int ks = 0; ks < 4; ++ks) {
            const int kw = ks * 8;
            unsigned Bh[2][2], Bl[2][2];
            #pragma unroll
            for (int ni = 0; ni < 2; ++ni) {
                const int rb = (n0 + ni * 8 + gq) * 36 + kw + q4;
                Bh[ni][0] = sBh[rb]; Bh[ni][1] = sBh[rb + 4];
                Bl[ni][0] = sBl[rb]; Bl[ni][1] = sBl[rb + 4];
            }
            unsigned Ah[2][4], Al[2][4];
            #pragma unroll
            for (int mi = 0; mi < 2; ++mi) {
                const int r0 = (m0 + mi * 16 + gq) * 36 + kw + q4;
                const int r8 = (m0 + mi * 16 + gq + 8) * 36 + kw + q4;
                Ah[mi][0] = sVh[r0];     Ah[mi][1] = sVh[r8];
                Ah[mi][2] = sVh[r0 + 4]; Ah[mi][3] = sVh[r8 + 4];
                Al[mi][0] = sVl[r0];     Al[mi][1] = sVl[r8];
                Al[mi][2] = sVl[r0 + 4]; Al[mi][3] = sVl[r8 + 4];
            }
            #pragma unroll
            for (int mi = 0; mi < 2; ++mi)
                #pragma unroll
                for (int ni = 0; ni < 2; ++ni) {
                    mma_bf16(Cv[mi][ni], Ah[mi], Bh[ni]);
                    mma_bf16(Cv[mi][ni], Ah[mi], Bl[ni]);
                    mma_bf16(Cv[mi][ni], Al[mi], Bh[ni]);
                }
            if (doSkk) {
                #pragma unroll
                for (int mi = 0; mi < 2; ++mi) {
                    const int r0 = (m0 + mi * 16 + gq) * 36 + kw + q4;
                    const int r8 = (m0 + mi * 16 + gq + 8) * 36 + kw + q4;
                    Ah[mi][0] = sKh[r0];     Ah[mi][1] = sKh[r8];
                    Ah[mi][2] = sKh[r0 + 4]; Ah[mi][3] = sKh[r8 + 4];
                    Al[mi][0] = sKl[r0];     Al[mi][1] = sKl[r8];
                    Al[mi][2] = sKl[r0 + 4]; Al[mi][3] = sKl[r8 + 4];
                }
                #pragma unroll
                for (int mi = 0; mi < 2; ++mi)
                    #pragma unroll
                    for (int ni = 0; ni < 2; ++ni) {
                        mma_bf16(Csm[mi][ni], Ah[mi], Bh[ni]);
                        mma_bf16(Csm[mi][ni], Ah[mi], Bl[ni]);
                        mma_bf16(Csm[mi][ni], Al[mi], Bh[ni]);
                    }
            }
        }
        __syncthreads();
    }

    float* svk = g_Svk + (long)n * MATSZ;
    #pragma unroll
    for (int mi = 0; mi < 2; ++mi)
        #pragma unroll
        for (int ni = 0; ni < 2; ++ni) {
            const int x0 = ib * 64 + m0 + mi * 16 + gq;
            const int y  = jb * 64 + n0 + ni * 8 + q4 * 2;
            *(float2*)(svk + (long)x0 * DD + y)       = make_float2(Cv[mi][ni][0], Cv[mi][ni][1]);
            *(float2*)(svk + (long)(x0 + 8) * DD + y) = make_float2(Cv[mi][ni][2], Cv[mi][ni][3]);
        }

    if (doSkk) {
        float* skk = g_Skk + (long)n * MATSZ;
        #pragma unroll
        for (int mi = 0; mi < 2; ++mi)
            #pragma unroll
            for (int ni = 0; ni < 2; ++ni) {
                const int x0 = ib * 64 + m0 + mi * 16 + gq;
                const int y  = jb * 64 + n0 + ni * 8 + q4 * 2;
                *(float2*)(skk + (long)x0 * DD + y)       = make_float2(Csm[mi][ni][0], Csm[mi][ni][1]);
                *(float2*)(skk + (long)(x0 + 8) * DD + y) = make_float2(Csm[mi][ni][2], Csm[mi][ni][3]);
                if (ib < jb) {
                    skk[(long)y * DD + x0]           = Csm[mi][ni][0];
                    skk[(long)(y + 1) * DD + x0]     = Csm[mi][ni][1];
                    skk[(long)y * DD + x0 + 8]       = Csm[mi][ni][2];
                    skk[(long)(y + 1) * DD + x0 + 8] = Csm[mi][ni][3];
                }
            }
    }
}

// ---------------------------------------------------------------------------
// Phase A: per-chunk local scan + prefix products (exact R5 version).
// ---------------------------------------------------------------------------
__global__ __launch_bounds__(256) void kA_local(const float* __restrict__ alpha_p)
{
    __shared__ float srow[8][DD];
    const int j  = threadIdx.x;
    const int c  = blockIdx.y;
    const int o0 = blockIdx.x * 4;
    const float a = 1.f / (1.f + expf(-alpha_p[0]));

    #pragma unroll
    for (int r = 0; r < 4; ++r) {
        srow[r][j] = 0.f;
        srow[4 + r][j] = (j == o0 + r) ? 1.f : 0.f;
    }
    __syncthreads();

    for (int s = 0; s < CS; ++s) {
        const int n = c * CS + s;
        const float* skk = g_Skk + (long)n * MATSZ;
        const float* svk = g_Svk + (long)n * MATSZ;

        const float sv0 = svk[(long)(o0 + 0) * DD + j];
        const float sv1 = svk[(long)(o0 + 1) * DD + j];
        const float sv2 = svk[(long)(o0 + 2) * DD + j];
        const float sv3 = svk[(long)(o0 + 3) * DD + j];

        u64 accM[4] = {0, 0, 0, 0};
        u64 accP[4] = {0, 0, 0, 0};

        float sb[16];
        #pragma unroll
        for (int u = 0; u < 16; ++u) sb[u] = skk[(long)u * DD + j];

        #pragma unroll
        for (int blk = 0; blk < 16; ++blk) {
            float sn[16];
            if (blk < 15) {
                const float* p = skk + (long)(blk + 1) * 16 * DD + j;
                #pragma unroll
                for (int u = 0; u < 16; ++u) sn[u] = p[(long)u * DD];
            } else {
                #pragma unroll
                for (int u = 0; u < 16; ++u) sn[u] = 0.f;
            }
            u64 sp[8];
            #pragma unroll
            for (int p = 0; p < 8; ++p) sp[p] = pack2f(sb[2 * p], sb[2 * p + 1]);

            const int db = blk * 16;
            #pragma unroll
            for (int r = 0; r < 4; ++r) {
                const u64* mrow = (const u64*)&srow[r][db];
                #pragma unroll
                for (int p = 0; p < 8; ++p) ffma2(accM[r], mrow[p], sp[p]);
            }
            #pragma unroll
            for (int r = 0; r < 4; ++r) {
                const u64* prow = (const u64*)&srow[4 + r][db];
                #pragma unroll
                for (int p = 0; p < 8; ++p) ffma2(accP[r], prow[p], sp[p]);
            }
            #pragma unroll
            for (int u = 0; u < 16; ++u) sb[u] = sn[u];
        }

        float nM[4], nP[4];
        const float svv[4] = {sv0, sv1, sv2, sv3};
        #pragma unroll
        for (int r = 0; r < 4; ++r) {
            nM[r] = a * srow[r][j] - hsum2(accM[r]) + svv[r];
            nP[r] = a * srow[4 + r][j] - hsum2(accP[r]);
        }
        __syncthreads();
        float* ms = g_Ms + (long)n * MATSZ;
        float* pp = g_P  + (long)n * MATSZ;
        #pragma unroll
        for (int r = 0; r < 4; ++r) {
            srow[r][j] = nM[r];
            srow[4 + r][j] = nP[r];
            ms[(long)(o0 + r) * DD + j] = nM[r];
            pp[(long)(o0 + r) * DD + j] = nP[r];
        }
        __syncthreads();
    }
}

// ---------------------------------------------------------------------------
// Tree init (R5): gather chunk-end summaries into ping-pong buffer 0.
// ---------------------------------------------------------------------------
__global__ __launch_bounds__(256) void kT_init()
{
    const int j  = threadIdx.x;
    const int c  = blockIdx.y;
    const int o0 = blockIdx.x * 4;
    const long src = (long)(c * CS + CS - 1) * MATSZ;
    const long dst = (long)c * MATSZ;
    #pragma unroll
    for (int r = 0; r < 4; ++r) {
        const long off = (long)(o0 + r) * DD + j;
        g_TP0[dst + off] = g_P [src + off];
        g_TS0[dst + off] = g_Ms[src + off];
    }
}

// ---------------------------------------------------------------------------
// Tree level (exact R5 scalar): Kogge-Stone over (P,S).
// ---------------------------------------------------------------------------
__global__ __launch_bounds__(256) void kT_combine(int stride, int srcIdx)
{
    const float* srcP = srcIdx ? g_TP1 : g_TP0;
    const float* srcS = srcIdx ? g_TS1 : g_TS0;
    float*       dstP = srcIdx ? g_TP0 : g_TP1;
    float*       dstS = srcIdx ? g_TS0 : g_TS1;

    const int c   = blockIdx.y;
    const int isS = blockIdx.z;
    const int ib  = blockIdx.x >> 2;
    const int jb  = blockIdx.x & 3;
    const int tid = threadIdx.x;

    const float* srcM = isS ? srcS : srcP;
    float*       dstM = isS ? dstS : dstP;

    if (c < stride) {
        const int lr = tid >> 2;
        const int lc = tid & 3;
        const long base = (long)c * MATSZ;
        #pragma unroll
        for (int it = 0; it < 4; ++it) {
            const long off = base + (long)(ib * 64 + lr) * DD + jb * 64 + (lc + it * 4) * 4;
            *(float4*)(dstM + off) = *(const float4*)(srcM + off);
        }
        return;
    }

    __shared__ float sA[16][68];
    __shared__ float sB[16][68];

    const int lr = tid >> 2;
    const int lc = tid & 3;
    const int pr = tid >> 4;
    const int pc = tid & 15;
    const int tx = tid & 15;
    const int ty = tid >> 4;

    const float* A  = srcM + (long)(c - stride) * MATSZ;
    const float* Bm = srcP + (long)c * MATSZ;
    float*       Dm = dstM + (long)c * MATSZ;

    float acc[4][4];
    #pragma unroll
    for (int r = 0; r < 4; ++r)
        #pragma unroll
        for (int q = 0; q < 4; ++q) acc[r][q] = 0.f;

    const long arow = (long)(ib * 64 + lr) * DD;

    float4 av = *(const float4*)(A + arow + lc * 4);
    float4 bv = *(const float4*)(Bm + (long)pr * DD + jb * 64 + pc * 4);

    for (int ch = 0; ch < 16; ++ch) {
        sA[lc * 4 + 0][lr] = av.x; sA[lc * 4 + 1][lr] = av.y;
        sA[lc * 4 + 2][lr] = av.z; sA[lc * 4 + 3][lr] = av.w;
        sB[pr][pc * 4 + 0] = bv.x; sB[pr][pc * 4 + 1] = bv.y;
        sB[pr][pc * 4 + 2] = bv.z; sB[pr][pc * 4 + 3] = bv.w;
        __syncthreads();

        if (ch < 15) {
            av = *(const float4*)(A + arow + (ch + 1) * 16 + lc * 4);
            bv = *(const float4*)(Bm + (long)((ch + 1) * 16 + pr) * DD + jb * 64 + pc * 4);
        }

        #pragma unroll
        for (int dk = 0; dk < 16; ++dk) {
            float aw[4], bw[4];
            #pragma unroll
            for (int r = 0; r < 4; ++r) aw[r] = sA[dk][ty * 4 + r];
            #pragma unroll
            for (int q = 0; q < 4; ++q) bw[q] = sB[dk][tx * 4 + q];
            #pragma unroll
            for (int r = 0; r < 4; ++r)
                #pragma unroll
                for (int q = 0; q < 4; ++q) acc[r][q] += aw[r] * bw[q];
        }
        __syncthreads();
    }

    const float* C0 = srcS + (long)c * MATSZ;
    #pragma unroll
    for (int r = 0; r < 4; ++r) {
        const long off = (long)(ib * 64 + ty * 4 + r) * DD + jb * 64 + tx * 4;
        float4 res = make_float4(acc[r][0], acc[r][1], acc[r][2], acc[r][3]);
        if (isS) {
            float4 cc = *(const float4*)(C0 + off);
            res.x += cc.x; res.y += cc.y; res.z += cc.z; res.w += cc.w;
        }
        *(float4*)(Dm + off) = res;
    }
}

// ---------------------------------------------------------------------------
// Phase C: Ms[n] += E_{c-1} @ P_n via bf16x3 MMA (R14 version).
// ---------------------------------------------------------------------------
__global__ __launch_bounds__(256) void kC_fix()
{
    __shared__ unsigned sAh[64 * 36], sAl[64 * 36];
    __shared__ unsigned sBh[64 * 36], sBl[64 * 36];

    const int nw  = blockIdx.y + CS;
    const int c   = nw / CS;
    const int ib  = blockIdx.x >> 2;
    const int jb  = blockIdx.x & 3;
    const int tid = threadIdx.x;
    const int wid = tid >> 5;
    const int lane = tid & 31;
    const int gq  = lane >> 2;
    const int q4  = lane & 3;

    const int m0 = (wid >> 2) * 32;
    const int n0 = (wid & 3) * 16;

    const int crow = tid >> 2;
    const int cseg = tid & 3;

    const long aw0 = (long)(c - 1) * MATW + (long)(ib * 64 + crow) * (DD / 2) + cseg * 8;
    const long bw0 = (long)nw * MATW + (long)(jb * 64 + crow) * (DD / 2) + cseg * 8;

    float C[2][2][4];
    #pragma unroll
    for (int mi = 0; mi < 2; ++mi)
        #pragma unroll
        for (int ni = 0; ni < 2; ++ni)
            #pragma unroll
            for (int e = 0; e < 4; ++e) C[mi][ni][e] = 0.f;

    for (int chu = 0; chu < 4; ++chu) {
        const int wbase = crow * 36 + cseg * 8;
        {
            uint4 a0 = *(const uint4*)(g_Eh + aw0 + chu * 32);
            uint4 a1 = *(const uint4*)(g_Eh + aw0 + chu * 32 + 4);
            uint4 l0 = *(const uint4*)(g_El + aw0 + chu * 32);
            uint4 l1 = *(const uint4*)(g_El + aw0 + chu * 32 + 4);
            sAh[wbase + 0] = a0.x; sAh[wbase + 1] = a0.y; sAh[wbase + 2] = a0.z; sAh[wbase + 3] = a0.w;
            sAh[wbase + 4] = a1.x; sAh[wbase + 5] = a1.y; sAh[wbase + 6] = a1.z; sAh[wbase + 7] = a1.w;
            sAl[wbase + 0] = l0.x; sAl[wbase + 1] = l0.y; sAl[wbase + 2] = l0.z; sAl[wbase + 3] = l0.w;
            sAl[wbase + 4] = l1.x; sAl[wbase + 5] = l1.y; sAl[wbase + 6] = l1.z; sAl[wbase + 7] = l1.w;
            uint4 b0 = *(const uint4*)(g_PTh + bw0 + chu * 32);
            uint4 b1 = *(const uint4*)(g_PTh + bw0 + chu * 32 + 4);
            uint4 m0v = *(const uint4*)(g_PTl + bw0 + chu * 32);
            uint4 m1v = *(const uint4*)(g_PTl + bw0 + chu * 32 + 4);
            sBh[wbase + 0] = b0.x; sBh[wbase + 1] = b0.y; sBh[wbase + 2] = b0.z; sBh[wbase + 3] = b0.w;
            sBh[wbase + 4] = b1.x; sBh[wbase + 5] = b1.y; sBh[wbase + 6] = b1.z; sBh[wbase + 7] = b1.w;
            sBl[wbase + 0] = m0v.x; sBl[wbase + 1] = m0v.y; sBl[wbase + 2] = m0v.z; sBl[wbase + 3] = m0v.w;
            sBl[wbase + 4] = m1v.x; sBl[wbase + 5] = m1v.y; sBl[wbase + 6] = m1v.z; sBl[wbase + 7] = m1v.w;
        }
        __syncthreads();

        #pragma unroll
        for (int ks = 0; ks < 4; ++ks) {
            const int kw = ks * 8;
            unsigned Ah[2][4], Al[2][4];
            #pragma unroll
            for (int mi = 0; mi < 2; ++mi) {
                const int r0 = (m0 + mi * 16 + gq) * 36 + kw + q4;
                const int r8 = (m0 + mi * 16 + gq + 8) * 36 + kw + q4;
                Ah[mi][0] = sAh[r0];     Ah[mi][1] = sAh[r8];
                Ah[mi][2] = sAh[r0 + 4]; Ah[mi][3] = sAh[r8 + 4];
                Al[mi][0] = sAl[r0];     Al[mi][1] = sAl[r8];
                Al[mi][2] = sAl[r0 + 4]; Al[mi][3] = sAl[r8 + 4];
            }
            unsigned Bh[2][2], Bl[2][2];
            #pragma unroll
            for (int ni = 0; ni < 2; ++ni) {
                const int rb = (n0 + ni * 8 + gq) * 36 + kw + q4;
                Bh[ni][0] = sBh[rb]; Bh[ni][1] = sBh[rb + 4];
                Bl[ni][0] = sBl[rb]; Bl[ni][1] = sBl[rb + 4];
            }
            #pragma unroll
            for (int mi = 0; mi < 2; ++mi)
                #pragma unroll
                for (int ni = 0; ni < 2; ++ni) {
                    mma_bf16(C[mi][ni], Ah[mi], Bh[ni]);
                    mma_bf16(C[mi][ni], Ah[mi], Bl[ni]);
                    mma_bf16(C[mi][ni], Al[mi], Bh[ni]);
                }
        }
        __syncthreads();
    }

    float* Ms = g_Ms + (long)nw * MATSZ;
    #pragma unroll
    for (int mi = 0; mi < 2; ++mi) {
        #pragma unroll
        for (int ni = 0; ni < 2; ++ni) {
            const int col = jb * 64 + n0 + ni * 8 + q4 * 2;
            const int x0 = ib * 64 + m0 + mi * 16 + gq;
            float2* d0 = (float2*)(Ms + (long)x0 * DD + col);
            float2* d8 = (float2*)(Ms + (long)(x0 + 8) * DD + col);
            float2 o0 = *d0, o8 = *d8;
            o0.x += C[mi][ni][0]; o0.y += C[mi][ni][1];
            o8.x += C[mi][ni][2]; o8.y += C[mi][ni][3];
            *d0 = o0; *d8 = o8;
        }
    }
}

// ---------------------------------------------------------------------------
// K3: retrieval via bf16x3 MMA, pre-converted operands (R14 version).
// ---------------------------------------------------------------------------
__global__ __launch_bounds__(256) void k3_out(float* __restrict__ out)
{
    __shared__ unsigned sQh[64 * 36], sQl[64 * 36];
    __shared__ unsigned sMh[64 * 36], sMl[64 * 36];

    const int n   = blockIdx.y;
    const int tb  = blockIdx.x >> 2;
    const int ob  = blockIdx.x & 3;
    const int tid = threadIdx.x;
    const int wid = tid >> 5;
    const int lane = tid & 31;
    const int gq  = lane >> 2;
    const int q4  = lane & 3;

    const int m0 = (wid >> 2) * 32;
    const int n0 = (wid & 3) * 16;

    const int crow = tid >> 2;
    const int cseg = tid & 3;

    const long qw0 = ((long)tb * LL + (long)n * WW + crow) * (DD / 2) + cseg * 8;
    const long mw0 = (long)n * MATW + (long)(ob * 64 + crow) * (DD / 2) + cseg * 8;

    float C[2][2][4];
    #pragma unroll
    for (int mi = 0; mi < 2; ++mi)
        #pragma unroll
        for (int ni = 0; ni < 2; ++ni)
            #pragma unroll
            for (int e = 0; e < 4; ++e) C[mi][ni][e] = 0.f;

    for (int chu = 0; chu < 4; ++chu) {
        const int wbase = crow * 36 + cseg * 8;
        {
            uint4 a0 = *(const uint4*)(g_Qh + qw0 + chu * 32);
            uint4 a1 = *(const uint4*)(g_Qh + qw0 + chu * 32 + 4);
            uint4 l0 = *(const uint4*)(g_Ql + qw0 + chu * 32);
            uint4 l1 = *(const uint4*)(g_Ql + qw0 + chu * 32 + 4);
            sQh[wbase + 0] = a0.x; sQh[wbase + 1] = a0.y; sQh[wbase + 2] = a0.z; sQh[wbase + 3] = a0.w;
            sQh[wbase + 4] = a1.x; sQh[wbase + 5] = a1.y; sQh[wbase + 6] = a1.z; sQh[wbase + 7] = a1.w;
            sQl[wbase + 0] = l0.x; sQl[wbase + 1] = l0.y; sQl[wbase + 2] = l0.z; sQl[wbase + 3] = l0.w;
            sQl[wbase + 4] = l1.x; sQl[wbase + 5] = l1.y; sQl[wbase + 6] = l1.z; sQl[wbase + 7] = l1.w;
            uint4 b0 = *(const uint4*)(g_Msh + mw0 + chu * 32);
            uint4 b1 = *(const uint4*)(g_Msh + mw0 + chu * 32 + 4);
            uint4 m0v = *(const uint4*)(g_Msl + mw0 + chu * 32);
            uint4 m1v = *(const uint4*)(g_Msl + mw0 + chu * 32 + 4);
            sMh[wbase + 0] = b0.x; sMh[wbase + 1] = b0.y; sMh[wbase + 2] = b0.z; sMh[wbase + 3] = b0.w;
            sMh[wbase + 4] = b1.x; sMh[wbase + 5] = b1.y; sMh[wbase + 6] = b1.z; sMh[wbase + 7] = b1.w;
            sMl[wbase + 0] = m0v.x; sMl[wbase + 1] = m0v.y; sMl[wbase + 2] = m0v.z; sMl[wbase + 3] = m0v.w;
            sMl[wbase + 4] = m1v.x; sMl[wbase + 5] = m1v.y; sMl[wbase + 6] = m1v.z; sMl[wbase + 7] = m1v.w;
        }
        __syncthreads();

        #pragma unroll
        for (int ks = 0; ks < 4; ++ks) {
            const int kw = ks * 8;
            unsigned Ah[2][4], Al[2][4];
            #pragma unroll
            for (int mi = 0; mi < 2; ++mi) {
                const int r0 = (m0 + mi * 16 + gq) * 36 + kw + q4;
                const int r8 = (m0 + mi * 16 + gq + 8) * 36 + kw + q4;
                Ah[mi][0] = sQh[r0];     Ah[mi][1] = sQh[r8];
                Ah[mi][2] = sQh[r0 + 4]; Ah[mi][3] = sQh[r8 + 4];
                Al[mi][0] = sQl[r0];     Al[mi][1] = sQl[r8];
                Al[mi][2] = sQl[r0 + 4]; Al[mi][3] = sQl[r8 + 4];
            }
            unsigned Bh[2][2], Bl[2][2];
            #pragma unroll
            for (int ni = 0; ni < 2; ++ni) {
                const int rb = (n0 + ni * 8 + gq) * 36 + kw + q4;
                Bh[ni][0] = sMh[rb]; Bh[ni][1] = sMh[rb + 4];
                Bl[ni][0] = sMl[rb]; Bl[ni][1] = sMl[rb + 4];
            }
            #pragma unroll
            for (int mi = 0; mi < 2; ++mi)
                #pragma unroll
                for (int ni = 0; ni < 2; ++ni) {
                    mma_bf16(C[mi][ni], Ah[mi], Bh[ni]);
                    mma_bf16(C[mi][ni], Ah[mi], Bl[ni]);
                    mma_bf16(C[mi][ni], Al[mi], Bh[ni]);
                }
        }
        __syncthreads();
    }

    #pragma unroll
    for (int mi = 0; mi < 2; ++mi) {
        #pragma unroll
        for (int ni = 0; ni < 2; ++ni) {
            const int ocol = ob * 64 + n0 + ni * 8 + q4 * 2;
            const int tl0 = m0 + mi * 16 + gq;
            float* d0 = out + ((long)tb * LL + (long)n * WW + tl0) * DD + ocol;
            float* d8 = out + ((long)tb * LL + (long)n * WW + tl0 + 8) * DD + ocol;
            *(float2*)d0 = make_float2(C[mi][ni][0], C[mi][ni][1]);
            *(float2*)d8 = make_float2(C[mi][ni][2], C[mi][ni][3]);
        }
    }
}

// ---------------------------------------------------------------------------
extern "C" void kernel_launch(void* const* d_in, const int* in_sizes, int n_in,
                              void* d_out, int out_size)
{
    const float* keys    = (const float*)d_in[0];
    const float* values  = (const float*)d_in[1];
    const float* queries = (const float*)d_in[2];
    const float* gammas  = (const float*)d_in[3];
    const float* alpha   = (const float*)d_in[4];
    float* out = (float*)d_out;

    static int k1_attr_done = 0;
    if (!k1_attr_done) {
        cudaFuncSetAttribute(k1_moments,
                             cudaFuncAttributeMaxDynamicSharedMemorySize, K1_SMEM);
        k1_attr_done = 1;
    }

    kConvQ<<<BB * LL * DD / 1024, 256>>>(queries);
    k1_moments<<<dim3(16, NW), 256, K1_SMEM>>>(keys, values, gammas);
    kA_local<<<dim3(64, CH), 256>>>(alpha);
    kTrP<<<dim3(64, NW - CS), dim3(32, 8)>>>();
    kT_init<<<dim3(64, CH), 256>>>();
    kT_combine<<<dim3(16, CH, 2), 256>>>(1, 0);  // buf0 -> buf1
    kT_combine<<<dim3(16, CH, 2), 256>>>(2, 1);  // buf1 -> buf0
    kT_combine<<<dim3(16, CH, 2), 256>>>(4, 0);  // buf0 -> buf1
    kT_combine<<<dim3(16, CH, 2), 256>>>(8, 1);  // buf1 -> buf0 (final: g_TS0)
    kTrE<<<CH * MATSZ / 1024, 256>>>();
    kC_fix<<<dim3(16, NW - CS), 256>>>();
    kConvM<<<NW * MATSZ / 1024, 256>>>();
    k3_out<<<dim3(32, NW), 256>>>(out);
}

// round 17
// speedup vs baseline: 1.1316x; 1.1316x over previous
#include <cuda_runtime.h>
#include <cuda_bf16.h>
#include <math.h>

// OmegaRule: B=8, L=8192, D=256, W=64 -> NW=128 windows, T=B*W=512 rows/window.
#define BB 8
#define LL 8192
#define DD 256
#define WW 64
#define NW 128
#define TT 512
#define CH 16    // chunks
#define CS 8     // windows per chunk (CH*CS == NW)
#define MATSZ (DD * DD)
#define MATW (MATSZ / 2)   // matrix size in bf16-pair words
#define K1_SMEM (6 * 64 * 36 * 4)
#define LW (LL / 2)        // per-(d,b) row length in pair-words

// Scratch (device globals; no allocation allowed).
__device__ float g_Skk[NW * MATSZ];
__device__ float g_Svk[NW * MATSZ];
__device__ float g_Ms [NW * MATSZ];
__device__ float g_P  [NW * MATSZ];
__device__ float g_TP0[CH * MATSZ];
__device__ float g_TP1[CH * MATSZ];
__device__ float g_TS0[CH * MATSZ];
__device__ float g_TS1[CH * MATSZ];
// bf16 hi/lo word-packed buffers (low half = even index)
__device__ __align__(16) unsigned g_Qh [BB * LL * DD / 2];
__device__ __align__(16) unsigned g_Ql [BB * LL * DD / 2];
__device__ __align__(16) unsigned g_Msh[NW * MATW];
__device__ __align__(16) unsigned g_Msl[NW * MATW];
__device__ __align__(16) unsigned g_PTh[NW * MATW];   // transposed P: PT[y][d]
__device__ __align__(16) unsigned g_PTl[NW * MATW];
__device__ __align__(16) unsigned g_Eh [CH * MATW];
__device__ __align__(16) unsigned g_El [CH * MATW];
// globally transposed k1 operands: [d][b][l] pair-packed along l
__device__ __align__(16) unsigned g_KTh[DD * BB * LW];
__device__ __align__(16) unsigned g_KTl[DD * BB * LW];
__device__ __align__(16) unsigned g_GVh[DD * BB * LW];
__device__ __align__(16) unsigned g_GVl[DD * BB * LW];
__device__ __align__(16) unsigned g_GKh[DD * BB * LW];
__device__ __align__(16) unsigned g_GKl[DD * BB * LW];

typedef unsigned long long u64;
__device__ __forceinline__ void ffma2(u64& acc, u64 a, u64 b) {
    asm("fma.rn.f32x2 %0, %1, %2, %0;" : "+l"(acc) : "l"(a), "l"(b));
}
__device__ __forceinline__ u64 pack2f(float x, float y) {
    u64 r; asm("mov.b64 %0, {%1, %2};" : "=l"(r) : "f"(x), "f"(y)); return r;
}
__device__ __forceinline__ void unpack2f(u64 v, float& x, float& y) {
    asm("mov.b64 {%0, %1}, %2;" : "=f"(x), "=f"(y) : "l"(v));
}
__device__ __forceinline__ float hsum2(u64 v) {
    float x, y; unpack2f(v, x, y); return x + y;
}

__device__ __forceinline__ unsigned pack_bf16(float x, float y) {
    __nv_bfloat162 h = __floats2bfloat162_rn(x, y);
    return *(unsigned*)&h;
}
__device__ __forceinline__ float bf_hi_f(float x) {
    return __bfloat162float(__float2bfloat16(x));
}

// m16n8k16 bf16 MMA, fp32 accumulate (row.col).
__device__ __forceinline__ void mma_bf16(float* c, const unsigned* a, const unsigned* b) {
    asm volatile(
        "mma.sync.aligned.m16n8k16.row.col.f32.bf16.bf16.f32 "
        "{%0,%1,%2,%3}, {%4,%5,%6,%7}, {%8,%9}, {%0,%1,%2,%3};"
        : "+f"(c[0]), "+f"(c[1]), "+f"(c[2]), "+f"(c[3])
        : "r"(a[0]), "r"(a[1]), "r"(a[2]), "r"(a[3]), "r"(b[0]), "r"(b[1]));
}

// ---------------------------------------------------------------------------
// Conversion kernels (bandwidth-bound).
// ---------------------------------------------------------------------------
__global__ __launch_bounds__(256) void kConvQ(const float* __restrict__ q)
{
    const long i = ((long)blockIdx.x * 256 + threadIdx.x) * 4;
    float4 v = *(const float4*)(q + i);
    float h0 = bf_hi_f(v.x), h1 = bf_hi_f(v.y), h2 = bf_hi_f(v.z), h3 = bf_hi_f(v.w);
    g_Qh[i / 2 + 0] = pack_bf16(v.x, v.y);
    g_Qh[i / 2 + 1] = pack_bf16(v.z, v.w);
    g_Ql[i / 2 + 0] = pack_bf16(v.x - h0, v.y - h1);
    g_Ql[i / 2 + 1] = pack_bf16(v.z - h2, v.w - h3);
}

__global__ __launch_bounds__(256) void kConvM()
{
    const long i = ((long)blockIdx.x * 256 + threadIdx.x) * 4;
    float4 v = *(const float4*)(g_Ms + i);
    float h0 = bf_hi_f(v.x), h1 = bf_hi_f(v.y), h2 = bf_hi_f(v.z), h3 = bf_hi_f(v.w);
    g_Msh[i / 2 + 0] = pack_bf16(v.x, v.y);
    g_Msh[i / 2 + 1] = pack_bf16(v.z, v.w);
    g_Msl[i / 2 + 0] = pack_bf16(v.x - h0, v.y - h1);
    g_Msl[i / 2 + 1] = pack_bf16(v.z - h2, v.w - h3);
}

__global__ __launch_bounds__(256) void kTrE()
{
    const long i = ((long)blockIdx.x * 256 + threadIdx.x) * 4;
    float4 v = *(const float4*)(g_TS0 + i);
    float h0 = bf_hi_f(v.x), h1 = bf_hi_f(v.y), h2 = bf_hi_f(v.z), h3 = bf_hi_f(v.w);
    g_Eh[i / 2 + 0] = pack_bf16(v.x, v.y);
    g_Eh[i / 2 + 1] = pack_bf16(v.z, v.w);
    g_El[i / 2 + 0] = pack_bf16(v.x - h0, v.y - h1);
    g_El[i / 2 + 1] = pack_bf16(v.z - h2, v.w - h3);
}

// Transpose+convert P (windows CS..NW-1): PT[y][d] = P[d][y], bf16 hi/lo.
__global__ void kTrP()
{
    __shared__ float tile[32][33];
    const int n  = CS + blockIdx.y;
    const int dB = (blockIdx.x & 7) * 32;
    const int yB = (blockIdx.x >> 3) * 32;
    const int tx = threadIdx.x, ty = threadIdx.y;

    const float* P = g_P + (long)n * MATSZ;
    #pragma unroll
    for (int j = 0; j < 4; ++j)
        tile[ty + j * 8][tx] = P[(long)(dB + ty + j * 8) * DD + yB + tx];
    __syncthreads();

    if (tx < 16) {
        #pragma unroll
        for (int j = 0; j < 4; ++j) {
            const int yl = ty + j * 8;
            const float e0 = tile[2 * tx][yl];
            const float e1 = tile[2 * tx + 1][yl];
            const long w = (long)n * MATW + (long)(yB + yl) * (DD / 2) + dB / 2 + tx;
            g_PTh[w] = pack_bf16(e0, e1);
            g_PTl[w] = pack_bf16(e0 - bf_hi_f(e0), e1 - bf_hi_f(e1));
        }
    }
}

// ---------------------------------------------------------------------------
// kTrKV: global transpose+convert of k1 operands.
//   [b][l][d] fp32  ->  [d][b][l] bf16 hi/lo pair-packed (pairs along l)
//   k -> KT;  gamma*v -> GV;  gamma*k -> GK
// grid = (2048 tiles: 8 over D x 256 over L, BB), block = (32, 8).
// ---------------------------------------------------------------------------
__global__ void kTrKV(const float* __restrict__ keys,
                      const float* __restrict__ values,
                      const float* __restrict__ gammas)
{
    __shared__ float tK[32][33], tV[32][33], tG[32][33];
    const int b  = blockIdx.y;
    const int dB = (blockIdx.x & 7) * 32;
    const int lB = (blockIdx.x >> 3) * 32;
    const int tx = threadIdx.x, ty = threadIdx.y;

    #pragma unroll
    for (int j = 0; j < 4; ++j) {
        const int l = lB + ty + j * 8;
        const float g = __ldg(&gammas[(long)b * LL + l]);
        const float kv = keys  [((long)b * LL + l) * DD + dB + tx];
        const float vv = values[((long)b * LL + l) * DD + dB + tx];
        tK[ty + j * 8][tx] = kv;
        tV[ty + j * 8][tx] = g * vv;
        tG[ty + j * 8][tx] = g * kv;
    }
    __syncthreads();

    if (tx < 16) {
        #pragma unroll
        for (int j = 0; j < 4; ++j) {
            const int dl = ty + j * 8;
            const long w = ((long)(dB + dl) * BB + b) * LW + lB / 2 + tx;
            float e0, e1;
            e0 = tK[2 * tx][dl]; e1 = tK[2 * tx + 1][dl];
            g_KTh[w] = pack_bf16(e0, e1);
            g_KTl[w] = pack_bf16(e0 - bf_hi_f(e0), e1 - bf_hi_f(e1));
            e0 = tV[2 * tx][dl]; e1 = tV[2 * tx + 1][dl];
            g_GVh[w] = pack_bf16(e0, e1);
            g_GVl[w] = pack_bf16(e0 - bf_hi_f(e0), e1 - bf_hi_f(e1));
            e0 = tG[2 * tx][dl]; e1 = tG[2 * tx + 1][dl];
            g_GKh[w] = pack_bf16(e0, e1);
            g_GKl[w] = pack_bf16(e0 - bf_hi_f(e0), e1 - bf_hi_f(e1));
        }
    }
}

// ---------------------------------------------------------------------------
// K1: per-window moment matrices via bf16x3 MMA, pre-transposed operands.
//   Svk[x][y] = sum_t (g v)[t][x] * k[t][y]   (all 16 tiles)
//   Skk[x][y] = sum_t (g k)[t][x] * k[t][y]   (ib<=jb, mirrored)
// Staging = pure uint4 copies from [d][b][l] buffers. Dynamic smem 55 KB.
// ---------------------------------------------------------------------------
__global__ __launch_bounds__(256) void k1_moments()
{
    extern __shared__ unsigned sm1[];
    unsigned* sBh = sm1;               // k  (y-block)
    unsigned* sBl = sBh + 2304;
    unsigned* sVh = sBl + 2304;        // g*v (x-block)
    unsigned* sVl = sVh + 2304;
    unsigned* sKh = sVl + 2304;        // g*k (x-block)
    unsigned* sKl = sKh + 2304;

    const int n   = blockIdx.y;
    const int ib  = blockIdx.x >> 2;
    const int jb  = blockIdx.x & 3;
    const bool doSkk = (ib <= jb);
    const int tid = threadIdx.x;
    const int wid = tid >> 5;
    const int lane = tid & 31;
    const int gq  = lane >> 2;
    const int q4  = lane & 3;
    const int m0  = (wid >> 2) * 32;
    const int n0  = (wid & 3) * 16;
    const int crow = tid >> 2;    // feature row in block 0..63
    const int cseg = tid & 3;     // 8-word segment

    float Cv[2][2][4], Csm[2][2][4];
    #pragma unroll
    for (int mi = 0; mi < 2; ++mi)
        #pragma unroll
        for (int ni = 0; ni < 2; ++ni)
            #pragma unroll
            for (int e = 0; e < 4; ++e) { Cv[mi][ni][e] = 0.f; Csm[mi][ni][e] = 0.f; }

    const int wbase = crow * 36 + cseg * 8;

    for (int chu = 0; chu < 8; ++chu) {   // batch b == chu
        // word bases in [d][b][l] layout for this window's 64-l range
        const long kb = ((long)(jb * 64 + crow) * BB + chu) * LW + n * 32 + cseg * 8;
        const long ab = ((long)(ib * 64 + crow) * BB + chu) * LW + n * 32 + cseg * 8;
        {
            uint4 x0 = *(const uint4*)(g_KTh + kb);
            uint4 x1 = *(const uint4*)(g_KTl + kb);
            *(uint4*)(sBh + wbase) = x0;
            *(uint4*)(sBl + wbase) = x1;
            uint4 y0 = *(const uint4*)(g_GVh + ab);
            uint4 y1 = *(const uint4*)(g_GVl + ab);
            *(uint4*)(sVh + wbase) = y0;
            *(uint4*)(sVl + wbase) = y1;
            uint4 x2 = *(const uint4*)(g_KTh + kb + 4);
            uint4 x3 = *(const uint4*)(g_KTl + kb + 4);
            *(uint4*)(sBh + wbase + 4) = x2;
            *(uint4*)(sBl + wbase + 4) = x3;
            uint4 y2 = *(const uint4*)(g_GVh + ab + 4);
            uint4 y3 = *(const uint4*)(g_GVl + ab + 4);
            *(uint4*)(sVh + wbase + 4) = y2;
            *(uint4*)(sVl + wbase + 4) = y3;
            if (doSkk) {
                uint4 z0 = *(const uint4*)(g_GKh + ab);
                uint4 z1 = *(const uint4*)(g_GKl + ab);
                uint4 z2 = *(const uint4*)(g_GKh + ab + 4);
                uint4 z3 = *(const uint4*)(g_GKl + ab + 4);
                *(uint4*)(sKh + wbase) = z0;
                *(uint4*)(sKl + wbase) = z1;
                *(uint4*)(sKh + wbase + 4) = z2;
                *(uint4*)(sKl + wbase + 4) = z3;
            }
        }
        __syncthreads();

        #pragma unroll
        for (int ks = 0; ks < 4; ++ks) {
            const int kw = ks * 8;
            unsigned Bh[2][2], Bl[2][2];
            #pragma unroll
            for (int ni = 0; ni < 2; ++ni) {
                const int rb = (n0 + ni * 8 + gq) * 36 + kw + q4;
                Bh[ni][0] = sBh[rb]; Bh[ni][1] = sBh[rb + 4];
                Bl[ni][0] = sBl[rb]; Bl[ni][1] = sBl[rb + 4];
            }
            unsigned Ah[2][4], Al[2][4];
            #pragma unroll
            for (int mi = 0; mi < 2; ++mi) {
                const int r0 = (m0 + mi * 16 + gq) * 36 + kw + q4;
                const int r8 = (m0 + mi * 16 + gq + 8) * 36 + kw + q4;
                Ah[mi][0] = sVh[r0];     Ah[mi][1] = sVh[r8];
                Ah[mi][2] = sVh[r0 + 4]; Ah[mi][3] = sVh[r8 + 4];
                Al[mi][0] = sVl[r0];     Al[mi][1] = sVl[r8];
                Al[mi][2] = sVl[r0 + 4]; Al[mi][3] = sVl[r8 + 4];
            }
            #pragma unroll
            for (int mi = 0; mi < 2; ++mi)
                #pragma unroll
                for (int ni = 0; ni < 2; ++ni) {
                    mma_bf16(Cv[mi][ni], Ah[mi], Bh[ni]);
                    mma_bf16(Cv[mi][ni], Ah[mi], Bl[ni]);
                    mma_bf16(Cv[mi][ni], Al[mi], Bh[ni]);
                }
            if (doSkk) {
                #pragma unroll
                for (int mi = 0; mi < 2; ++mi) {
                    const int r0 = (m0 + mi * 16 + gq) * 36 + kw + q4;
                    const int r8 = (m0 + mi * 16 + gq + 8) * 36 + kw + q4;
                    Ah[mi][0] = sKh[r0];     Ah[mi][1] = sKh[r8];
                    Ah[mi][2] = sKh[r0 + 4]; Ah[mi][3] = sKh[r8 + 4];
                    Al[mi][0] = sKl[r0];     Al[mi][1] = sKl[r8];
                    Al[mi][2] = sKl[r0 + 4]; Al[mi][3] = sKl[r8 + 4];
                }
                #pragma unroll
                for (int mi = 0; mi < 2; ++mi)
                    #pragma unroll
                    for (int ni = 0; ni < 2; ++ni) {
                        mma_bf16(Csm[mi][ni], Ah[mi], Bh[ni]);
                        mma_bf16(Csm[mi][ni], Ah[mi], Bl[ni]);
                        mma_bf16(Csm[mi][ni], Al[mi], Bh[ni]);
                    }
            }
        }
        __syncthreads();
    }

    float* svk = g_Svk + (long)n * MATSZ;
    #pragma unroll
    for (int mi = 0; mi < 2; ++mi)
        #pragma unroll
        for (int ni = 0; ni < 2; ++ni) {
            const int x0 = ib * 64 + m0 + mi * 16 + gq;
            const int y  = jb * 64 + n0 + ni * 8 + q4 * 2;
            *(float2*)(svk + (long)x0 * DD + y)       = make_float2(Cv[mi][ni][0], Cv[mi][ni][1]);
            *(float2*)(svk + (long)(x0 + 8) * DD + y) = make_float2(Cv[mi][ni][2], Cv[mi][ni][3]);
        }

    if (doSkk) {
        float* skk = g_Skk + (long)n * MATSZ;
        #pragma unroll
        for (int mi = 0; mi < 2; ++mi)
            #pragma unroll
            for (int ni = 0; ni < 2; ++ni) {
                const int x0 = ib * 64 + m0 + mi * 16 + gq;
                const int y  = jb * 64 + n0 + ni * 8 + q4 * 2;
                *(float2*)(skk + (long)x0 * DD + y)       = make_float2(Csm[mi][ni][0], Csm[mi][ni][1]);
                *(float2*)(skk + (long)(x0 + 8) * DD + y) = make_float2(Csm[mi][ni][2], Csm[mi][ni][3]);
                if (ib < jb) {
                    skk[(long)y * DD + x0]           = Csm[mi][ni][0];
                    skk[(long)(y + 1) * DD + x0]     = Csm[mi][ni][1];
                    skk[(long)y * DD + x0 + 8]       = Csm[mi][ni][2];
                    skk[(long)(y + 1) * DD + x0 + 8] = Csm[mi][ni][3];
                }
            }
    }
}

// ---------------------------------------------------------------------------
// Phase A: per-chunk local scan + prefix products (exact R5 version).
// ---------------------------------------------------------------------------
__global__ __launch_bounds__(256) void kA_local(const float* __restrict__ alpha_p)
{
    __shared__ float srow[8][DD];
    const int j  = threadIdx.x;
    const int c  = blockIdx.y;
    const int o0 = blockIdx.x * 4;
    const float a = 1.f / (1.f + expf(-alpha_p[0]));

    #pragma unroll
    for (int r = 0; r < 4; ++r) {
        srow[r][j] = 0.f;
        srow[4 + r][j] = (j == o0 + r) ? 1.f : 0.f;
    }
    __syncthreads();

    for (int s = 0; s < CS; ++s) {
        const int n = c * CS + s;
        const float* skk = g_Skk + (long)n * MATSZ;
        const float* svk = g_Svk + (long)n * MATSZ;

        const float sv0 = svk[(long)(o0 + 0) * DD + j];
        const float sv1 = svk[(long)(o0 + 1) * DD + j];
        const float sv2 = svk[(long)(o0 + 2) * DD + j];
        const float sv3 = svk[(long)(o0 + 3) * DD + j];

        u64 accM[4] = {0, 0, 0, 0};
        u64 accP[4] = {0, 0, 0, 0};

        float sb[16];
        #pragma unroll
        for (int u = 0; u < 16; ++u) sb[u] = skk[(long)u * DD + j];

        #pragma unroll
        for (int blk = 0; blk < 16; ++blk) {
            float sn[16];
            if (blk < 15) {
                const float* p = skk + (long)(blk + 1) * 16 * DD + j;
                #pragma unroll
                for (int u = 0; u < 16; ++u) sn[u] = p[(long)u * DD];
            } else {
                #pragma unroll
                for (int u = 0; u < 16; ++u) sn[u] = 0.f;
            }
            u64 sp[8];
            #pragma unroll
            for (int p = 0; p < 8; ++p) sp[p] = pack2f(sb[2 * p], sb[2 * p + 1]);

            const int db = blk * 16;
            #pragma unroll
            for (int r = 0; r < 4; ++r) {
                const u64* mrow = (const u64*)&srow[r][db];
                #pragma unroll
                for (int p = 0; p < 8; ++p) ffma2(accM[r], mrow[p], sp[p]);
            }
            #pragma unroll
            for (int r = 0; r < 4; ++r) {
                const u64* prow = (const u64*)&srow[4 + r][db];
                #pragma unroll
                for (int p = 0; p < 8; ++p) ffma2(accP[r], prow[p], sp[p]);
            }
            #pragma unroll
            for (int u = 0; u < 16; ++u) sb[u] = sn[u];
        }

        float nM[4], nP[4];
        const float svv[4] = {sv0, sv1, sv2, sv3};
        #pragma unroll
        for (int r = 0; r < 4; ++r) {
            nM[r] = a * srow[r][j] - hsum2(accM[r]) + svv[r];
            nP[r] = a * srow[4 + r][j] - hsum2(accP[r]);
        }
        __syncthreads();
        float* ms = g_Ms + (long)n * MATSZ;
        float* pp = g_P  + (long)n * MATSZ;
        #pragma unroll
        for (int r = 0; r < 4; ++r) {
            srow[r][j] = nM[r];
            srow[4 + r][j] = nP[r];
            ms[(long)(o0 + r) * DD + j] = nM[r];
            pp[(long)(o0 + r) * DD + j] = nP[r];
        }
        __syncthreads();
    }
}

// ---------------------------------------------------------------------------
// Tree init (R5): gather chunk-end summaries into ping-pong buffer 0.
// ---------------------------------------------------------------------------
__global__ __launch_bounds__(256) void kT_init()
{
    const int j  = threadIdx.x;
    const int c  = blockIdx.y;
    const int o0 = blockIdx.x * 4;
    const long src = (long)(c * CS + CS - 1) * MATSZ;
    const long dst = (long)c * MATSZ;
    #pragma unroll
    for (int r = 0; r < 4; ++r) {
        const long off = (long)(o0 + r) * DD + j;
        g_TP0[dst + off] = g_P [src + off];
        g_TS0[dst + off] = g_Ms[src + off];
    }
}

// ---------------------------------------------------------------------------
// Tree level (exact R5 scalar): Kogge-Stone over (P,S).
// ---------------------------------------------------------------------------
__global__ __launch_bounds__(256) void kT_combine(int stride, int srcIdx)
{
    const float* srcP = srcIdx ? g_TP1 : g_TP0;
    const float* srcS = srcIdx ? g_TS1 : g_TS0;
    float*       dstP = srcIdx ? g_TP0 : g_TP1;
    float*       dstS = srcIdx ? g_TS0 : g_TS1;

    const int c   = blockIdx.y;
    const int isS = blockIdx.z;
    const int ib  = blockIdx.x >> 2;
    const int jb  = blockIdx.x & 3;
    const int tid = threadIdx.x;

    const float* srcM = isS ? srcS : srcP;
    float*       dstM = isS ? dstS : dstP;

    if (c < stride) {
        const int lr = tid >> 2;
        const int lc = tid & 3;
        const long base = (long)c * MATSZ;
        #pragma unroll
        for (int it = 0; it < 4; ++it) {
            const long off = base + (long)(ib * 64 + lr) * DD + jb * 64 + (lc + it * 4) * 4;
            *(float4*)(dstM + off) = *(const float4*)(srcM + off);
        }
        return;
    }

    __shared__ float sA[16][68];
    __shared__ float sB[16][68];

    const int lr = tid >> 2;
    const int lc = tid & 3;
    const int pr = tid >> 4;
    const int pc = tid & 15;
    const int tx = tid & 15;
    const int ty = tid >> 4;

    const float* A  = srcM + (long)(c - stride) * MATSZ;
    const float* Bm = srcP + (long)c * MATSZ;
    float*       Dm = dstM + (long)c * MATSZ;

    float acc[4][4];
    #pragma unroll
    for (int r = 0; r < 4; ++r)
        #pragma unroll
        for (int q = 0; q < 4; ++q) acc[r][q] = 0.f;

    const long arow = (long)(ib * 64 + lr) * DD;

    float4 av = *(const float4*)(A + arow + lc * 4);
    float4 bv = *(const float4*)(Bm + (long)pr * DD + jb * 64 + pc * 4);

    for (int ch = 0; ch < 16; ++ch) {
        sA[lc * 4 + 0][lr] = av.x; sA[lc * 4 + 1][lr] = av.y;
        sA[lc * 4 + 2][lr] = av.z; sA[lc * 4 + 3][lr] = av.w;
        sB[pr][pc * 4 + 0] = bv.x; sB[pr][pc * 4 + 1] = bv.y;
        sB[pr][pc * 4 + 2] = bv.z; sB[pr][pc * 4 + 3] = bv.w;
        __syncthreads();

        if (ch < 15) {
            av = *(const float4*)(A + arow + (ch + 1) * 16 + lc * 4);
            bv = *(const float4*)(Bm + (long)((ch + 1) * 16 + pr) * DD + jb * 64 + pc * 4);
        }

        #pragma unroll
        for (int dk = 0; dk < 16; ++dk) {
            float aw[4], bw[4];
            #pragma unroll
            for (int r = 0; r < 4; ++r) aw[r] = sA[dk][ty * 4 + r];
            #pragma unroll
            for (int q = 0; q < 4; ++q) bw[q] = sB[dk][tx * 4 + q];
            #pragma unroll
            for (int r = 0; r < 4; ++r)
                #pragma unroll
                for (int q = 0; q < 4; ++q) acc[r][q] += aw[r] * bw[q];
        }
        __syncthreads();
    }

    const float* C0 = srcS + (long)c * MATSZ;
    #pragma unroll
    for (int r = 0; r < 4; ++r) {
        const long off = (long)(ib * 64 + ty * 4 + r) * DD + jb * 64 + tx * 4;
        float4 res = make_float4(acc[r][0], acc[r][1], acc[r][2], acc[r][3]);
        if (isS) {
            float4 cc = *(const float4*)(C0 + off);
            res.x += cc.x; res.y += cc.y; res.z += cc.z; res.w += cc.w;
        }
        *(float4*)(Dm + off) = res;
    }
}

// ---------------------------------------------------------------------------
// Phase C: Ms[n] += E_{c-1} @ P_n via bf16x3 MMA (R14 version).
// ---------------------------------------------------------------------------
__global__ __launch_bounds__(256) void kC_fix()
{
    __shared__ unsigned sAh[64 * 36], sAl[64 * 36];
    __shared__ unsigned sBh[64 * 36], sBl[64 * 36];

    const int nw  = blockIdx.y + CS;
    const int c   = nw / CS;
    const int ib  = blockIdx.x >> 2;
    const int jb  = blockIdx.x & 3;
    const int tid = threadIdx.x;
    const int wid = tid >> 5;
    const int lane = tid & 31;
    const int gq  = lane >> 2;
    const int q4  = lane & 3;

    const int m0 = (wid >> 2) * 32;
    const int n0 = (wid & 3) * 16;

    const int crow = tid >> 2;
    const int cseg = tid & 3;

    const long aw0 = (long)(c - 1) * MATW + (long)(ib * 64 + crow) * (DD / 2) + cseg * 8;
    const long bw0 = (long)nw * MATW + (long)(jb * 64 + crow) * (DD / 2) + cseg * 8;

    float C[2][2][4];
    #pragma unroll
    for (int mi = 0; mi < 2; ++mi)
        #pragma unroll
        for (int ni = 0; ni < 2; ++ni)
            #pragma unroll
            for (int e = 0; e < 4; ++e) C[mi][ni][e] = 0.f;

    for (int chu = 0; chu < 4; ++chu) {
        const int wbase = crow * 36 + cseg * 8;
        {
            uint4 a0 = *(const uint4*)(g_Eh + aw0 + chu * 32);
            uint4 a1 = *(const uint4*)(g_Eh + aw0 + chu * 32 + 4);
            uint4 l0 = *(const uint4*)(g_El + aw0 + chu * 32);
            uint4 l1 = *(const uint4*)(g_El + aw0 + chu * 32 + 4);
            sAh[wbase + 0] = a0.x; sAh[wbase + 1] = a0.y; sAh[wbase + 2] = a0.z; sAh[wbase + 3] = a0.w;
            sAh[wbase + 4] = a1.x; sAh[wbase + 5] = a1.y; sAh[wbase + 6] = a1.z; sAh[wbase + 7] = a1.w;
            sAl[wbase + 0] = l0.x; sAl[wbase + 1] = l0.y; sAl[wbase + 2] = l0.z; sAl[wbase + 3] = l0.w;
            sAl[wbase + 4] = l1.x; sAl[wbase + 5] = l1.y; sAl[wbase + 6] = l1.z; sAl[wbase + 7] = l1.w;
            uint4 b0 = *(const uint4*)(g_PTh + bw0 + chu * 32);
            uint4 b1 = *(const uint4*)(g_PTh + bw0 + chu * 32 + 4);
            uint4 m0v = *(const uint4*)(g_PTl + bw0 + chu * 32);
            uint4 m1v = *(const uint4*)(g_PTl + bw0 + chu * 32 + 4);
            sBh[wbase + 0] = b0.x; sBh[wbase + 1] = b0.y; sBh[wbase + 2] = b0.z; sBh[wbase + 3] = b0.w;
            sBh[wbase + 4] = b1.x; sBh[wbase + 5] = b1.y; sBh[wbase + 6] = b1.z; sBh[wbase + 7] = b1.w;
            sBl[wbase + 0] = m0v.x; sBl[wbase + 1] = m0v.y; sBl[wbase + 2] = m0v.z; sBl[wbase + 3] = m0v.w;
            sBl[wbase + 4] = m1v.x; sBl[wbase + 5] = m1v.y; sBl[wbase + 6] = m1v.z; sBl[wbase + 7] = m1v.w;
        }
        __syncthreads();

        #pragma unroll
        for (int ks = 0; ks < 4; ++ks) {
            const int kw = ks * 8;
            unsigned Ah[2][4], Al[2][4];
            #pragma unroll
            for (int mi = 0; mi < 2; ++mi) {
                const int r0 = (m0 + mi * 16 + gq) * 36 + kw + q4;
                const int r8 = (m0 + mi * 16 + gq + 8) * 36 + kw + q4;
                Ah[mi][0] = sAh[r0];     Ah[mi][1] = sAh[r8];
                Ah[mi][2] = sAh[r0 + 4]; Ah[mi][3] = sAh[r8 + 4];
                Al[mi][0] = sAl[r0];     Al[mi][1] = sAl[r8];
                Al[mi][2] = sAl[r0 + 4]; Al[mi][3] = sAl[r8 + 4];
            }
            unsigned Bh[2][2], Bl[2][2];
            #pragma unroll
            for (int ni = 0; ni < 2; ++ni) {
                const int rb = (n0 + ni * 8 + gq) * 36 + kw + q4;
                Bh[ni][0] = sBh[rb]; Bh[ni][1] = sBh[rb + 4];
                Bl[ni][0] = sBl[rb]; Bl[ni][1] = sBl[rb + 4];
            }
            #pragma unroll
            for (int mi = 0; mi < 2; ++mi)
                #pragma unroll
                for (int ni = 0; ni < 2; ++ni) {
                    mma_bf16(C[mi][ni], Ah[mi], Bh[ni]);
                    mma_bf16(C[mi][ni], Ah[mi], Bl[ni]);
                    mma_bf16(C[mi][ni], Al[mi], Bh[ni]);
                }
        }
        __syncthreads();
    }

    float* Ms = g_Ms + (long)nw * MATSZ;
    #pragma unroll
    for (int mi = 0; mi < 2; ++mi) {
        #pragma unroll
        for (int ni = 0; ni < 2; ++ni) {
            const int col = jb * 64 + n0 + ni * 8 + q4 * 2;
            const int x0 = ib * 64 + m0 + mi * 16 + gq;
            float2* d0 = (float2*)(Ms + (long)x0 * DD + col);
            float2* d8 = (float2*)(Ms + (long)(x0 + 8) * DD + col);
            float2 o0 = *d0, o8 = *d8;
            o0.x += C[mi][ni][0]; o0.y += C[mi][ni][1];
            o8.x += C[mi][ni][2]; o8.y += C[mi][ni][3];
            *d0 = o0; *d8 = o8;
        }
    }
}

// ---------------------------------------------------------------------------
// K3: retrieval via bf16x3 MMA, pre-converted operands (R14 version).
// ---------------------------------------------------------------------------
__global__ __launch_bounds__(256) void k3_out(float* __restrict__ out)
{
    __shared__ unsigned sQh[64 * 36], sQl[64 * 36];
    __shared__ unsigned sMh[64 * 36], sMl[64 * 36];

    const int n   = blockIdx.y;
    const int tb  = blockIdx.x >> 2;
    const int ob  = blockIdx.x & 3;
    const int tid = threadIdx.x;
    const int wid = tid >> 5;
    const int lane = tid & 31;
    const int gq  = lane >> 2;
    const int q4  = lane & 3;

    const int m0 = (wid >> 2) * 32;
    const int n0 = (wid & 3) * 16;

    const int crow = tid >> 2;
    const int cseg = tid & 3;

    const long qw0 = ((long)tb * LL + (long)n * WW + crow) * (DD / 2) + cseg * 8;
    const long mw0 = (long)n * MATW + (long)(ob * 64 + crow) * (DD / 2) + cseg * 8;

    float C[2][2][4];
    #pragma unroll
    for (int mi = 0; mi < 2; ++mi)
        #pragma unroll
        for (int ni = 0; ni < 2; ++ni)
            #pragma unroll
            for (int e = 0; e < 4; ++e) C[mi][ni][e] = 0.f;

    for (int chu = 0; chu < 4; ++chu) {
        const int wbase = crow * 36 + cseg * 8;
        {
            uint4 a0 = *(const uint4*)(g_Qh + qw0 + chu * 32);
            uint4 a1 = *(const uint4*)(g_Qh + qw0 + chu * 32 + 4);
            uint4 l0 = *(const uint4*)(g_Ql + qw0 + chu * 32);
            uint4 l1 = *(const uint4*)(g_Ql + qw0 + chu * 32 + 4);
            sQh[wbase + 0] = a0.x; sQh[wbase + 1] = a0.y; sQh[wbase + 2] = a0.z; sQh[wbase + 3] = a0.w;
            sQh[wbase + 4] = a1.x; sQh[wbase + 5] = a1.y; sQh[wbase + 6] = a1.z; sQh[wbase + 7] = a1.w;
            sQl[wbase + 0] = l0.x; sQl[wbase + 1] = l0.y; sQl[wbase + 2] = l0.z; sQl[wbase + 3] = l0.w;
            sQl[wbase + 4] = l1.x; sQl[wbase + 5] = l1.y; sQl[wbase + 6] = l1.z; sQl[wbase + 7] = l1.w;
            uint4 b0 = *(const uint4*)(g_Msh + mw0 + chu * 32);
            uint4 b1 = *(const uint4*)(g_Msh + mw0 + chu * 32 + 4);
            uint4 m0v = *(const uint4*)(g_Msl + mw0 + chu * 32);
            uint4 m1v = *(const uint4*)(g_Msl + mw0 + chu * 32 + 4);
            sMh[wbase + 0] = b0.x; sMh[wbase + 1] = b0.y; sMh[wbase + 2] = b0.z; sMh[wbase + 3] = b0.w;
            sMh[wbase + 4] = b1.x; sMh[wbase + 5] = b1.y; sMh[wbase + 6] = b1.z; sMh[wbase + 7] = b1.w;
            sMl[wbase + 0] = m0v.x; sMl[wbase + 1] = m0v.y; sMl[wbase + 2] = m0v.z; sMl[wbase + 3] = m0v.w;
            sMl[wbase + 4] = m1v.x; sMl[wbase + 5] = m1v.y; sMl[wbase + 6] = m1v.z; sMl[wbase + 7] = m1v.w;
        }
        __syncthreads();

        #pragma unroll
        for (int ks = 0; ks < 4; ++ks) {
            const int kw = ks * 8;
            unsigned Ah[2][4], Al[2][4];
            #pragma unroll
            for (int mi = 0; mi < 2; ++mi) {
                const int r0 = (m0 + mi * 16 + gq) * 36 + kw + q4;
                const int r8 = (m0 + mi * 16 + gq + 8) * 36 + kw + q4;
                Ah[mi][0] = sQh[r0];     Ah[mi][1] = sQh[r8];
                Ah[mi][2] = sQh[r0 + 4]; Ah[mi][3] = sQh[r8 + 4];
                Al[mi][0] = sQl[r0];     Al[mi][1] = sQl[r8];
                Al[mi][2] = sQl[r0 + 4]; Al[mi][3] = sQl[r8 + 4];
            }
            unsigned Bh[2][2], Bl[2][2];
            #pragma unroll
            for (int ni = 0; ni < 2; ++ni) {
                const int rb = (n0 + ni * 8 + gq) * 36 + kw + q4;
                Bh[ni][0] = sMh[rb]; Bh[ni][1] = sMh[rb + 4];
                Bl[ni][0] = sMl[rb]; Bl[ni][1] = sMl[rb + 4];
            }
            #pragma unroll
            for (int mi = 0; mi < 2; ++mi)
                #pragma unroll
                for (int ni = 0; ni < 2; ++ni) {
                    mma_bf16(C[mi][ni], Ah[mi], Bh[ni]);
                    mma_bf16(C[mi][ni], Ah[mi], Bl[ni]);
                    mma_bf16(C[mi][ni], Al[mi], Bh[ni]);
                }
        }
        __syncthreads();
    }

    #pragma unroll
    for (int mi = 0; mi < 2; ++mi) {
        #pragma unroll
        for (int ni = 0; ni < 2; ++ni) {
            const int ocol = ob * 64 + n0 + ni * 8 + q4 * 2;
            const int tl0 = m0 + mi * 16 + gq;
            float* d0 = out + ((long)tb * LL + (long)n * WW + tl0) * DD + ocol;
            float* d8 = out + ((long)tb * LL + (long)n * WW + tl0 + 8) * DD + ocol;
            *(float2*)d0 = make_float2(C[mi][ni][0], C[mi][ni][1]);
            *(float2*)d8 = make_float2(C[mi][ni][2], C[mi][ni][3]);
        }
    }
}

// ---------------------------------------------------------------------------
extern "C" void kernel_launch(void* const* d_in, const int* in_sizes, int n_in,
                              void* d_out, int out_size)
{
    const float* keys    = (const float*)d_in[0];
    const float* values  = (const float*)d_in[1];
    const float* queries = (const float*)d_in[2];
    const float* gammas  = (const float*)d_in[3];
    const float* alpha   = (const float*)d_in[4];
    float* out = (float*)d_out;

    static int k1_attr_done = 0;
    if (!k1_attr_done) {
        cudaFuncSetAttribute(k1_moments,
                             cudaFuncAttributeMaxDynamicSharedMemorySize, K1_SMEM);
        k1_attr_done = 1;
    }

    kConvQ<<<BB * LL * DD / 1024, 256>>>(queries);
    kTrKV<<<dim3(2048, BB), dim3(32, 8)>>>(keys, values, gammas);
    k1_moments<<<dim3(16, NW), 256, K1_SMEM>>>();
    kA_local<<<dim3(64, CH), 256>>>(alpha);
    kTrP<<<dim3(64, NW - CS), dim3(32, 8)>>>();
    kT_init<<<dim3(64, CH), 256>>>();
    kT_combine<<<dim3(16, CH, 2), 256>>>(1, 0);  // buf0 -> buf1
    kT_combine<<<dim3(16, CH, 2), 256>>>(2, 1);  // buf1 -> buf0
    kT_combine<<<dim3(16, CH, 2), 256>>>(4, 0);  // buf0 -> buf1
    kT_combine<<<dim3(16, CH, 2), 256>>>(8, 1);  // buf1 -> buf0 (final: g_TS0)
    kTrE<<<CH * MATSZ / 1024, 256>>>();
    kC_fix<<<dim3(16, NW - CS), 256>>>();
    kConvM<<<NW * MATSZ / 1024, 256>>>();
    k3_out<<<dim3(32, NW), 256>>>(out);
}